// round 10
// baseline (speedup 1.0000x reference)
#include <cuda_runtime.h>
#include <cstddef>

#define KCODES 1024
#define DDIM   256
#define NPIX   65536
#define THREADS 256
#define MARGIN  7.5e-5f

// ---- wide main kernel geometry (2 CTAs/SM) ----
#define BPW 64       // pixels per block
#define TKW 128      // codes per tile
#define DCW 32       // d per chunk
#define SEW 132      // e_s row stride (128 codes + pad)
#define ZW_OFF  0                        // 16384 floats
#define EW_OFF  16384                    // 4224
#define ENW_OFF (16384 + 4224)           // 1024
#define AW_OFF  (ENW_OFF + 1024)         // 64
#define SMEMW_FLOATS (AW_OFF + 64)       // 21696 floats = 86,784 B

__device__ float g_enorm[KCODES];
__device__ float g_A[NPIX];
__device__ int   g_nflag;
__device__ int   g_flags[NPIX];

#define FMA2(a, x, y) \
    asm("fma.rn.f32x2 %0, %1, %2, %0;" : "+l"(a) : "l"(x), "l"(y))
#define DUP2(d, s) \
    asm("mov.b64 %0, {%1,%1};" : "=l"(d) : "f"(s))

// ---------------------------------------------------------------------------
// Emulated reference row sum-of-squares (proven exact R7-R9).
// ---------------------------------------------------------------------------
__device__ __forceinline__ float sumsq_emul(const float* x, long stride) {
    float S[8];
#pragma unroll
    for (int l = 0; l < 8; l++) S[l] = 0.f;
    for (int t = 0; t < DDIM / 8; t++) {
#pragma unroll
        for (int l = 0; l < 8; l++) {
            float v = x[(long)(8 * t + l) * stride];
            S[l] = __fadd_rn(S[l], __fmul_rn(v, v));
        }
    }
    float m0 = __fadd_rn(S[0], S[4]);
    float m1 = __fadd_rn(S[1], S[5]);
    float m2 = __fadd_rn(S[2], S[6]);
    float m3 = __fadd_rn(S[3], S[7]);
    return __fadd_rn(__fadd_rn(m0, m1), __fadd_rn(m2, m3));
}

__global__ void reset_kernel() { if (threadIdx.x == 0) g_nflag = 0; }

__global__ void enorm_kernel(const float* __restrict__ emb) {
    int c = blockIdx.x * blockDim.x + threadIdx.x;
    if (c < KCODES) g_enorm[c] = sumsq_emul(emb + (size_t)c * DDIM, 1);
}

__global__ void anorm_kernel(const float* __restrict__ z) {
    int p = blockIdx.x * blockDim.x + threadIdx.x;
    if (p < NPIX) {
        const float* zp = z + (size_t)(p >> 12) * (DDIM * 4096) + (p & 4095);
        g_A[p] = sumsq_emul(zp, 4096);
    }
}

// ---------------------------------------------------------------------------
// Main pass: packed f32x2, 64 px/block, 8 px x 4 codes per thread, 2 CTAs/SM.
// ---------------------------------------------------------------------------
__global__ __launch_bounds__(THREADS, 2)
void vq_wide(const float* __restrict__ z, const float* __restrict__ emb,
             float* __restrict__ out) {
    extern __shared__ float smem[];
    float* z_s  = smem + ZW_OFF;
    float* e_s  = smem + EW_OFF;
    float* en_s = smem + ENW_OFF;
    float* A_s  = smem + AW_OFF;

    const int tid = threadIdx.x;
    const int tx  = tid & 7;     // 8 groups x 8 px  = 64 px
    const int ty  = tid >> 3;    // 32 groups x 4 cd = 128 codes/tile

    const int n0 = blockIdx.x * BPW;   // 64 | 4096 -> never crosses batch
    const float* zbase = z + (size_t)(n0 >> 12) * (DDIM * 4096) + (n0 & 4095);

    // ---- z tile [256][64], coalesced ----
#pragma unroll
    for (int it = 0; it < 16; it++) {
        int idx = it * THREADS + tid;          // 4096 float4 slots
        int d = idx >> 4, c4 = (idx & 15) << 2;
        *(float4*)(z_s + d * BPW + c4) =
            *(const float4*)(zbase + (size_t)d * 4096 + c4);
    }
    for (int i = tid; i < KCODES; i += THREADS) en_s[i] = g_enorm[i];
    if (tid < BPW) A_s[tid] = g_A[n0 + tid];
    __syncthreads();

    float A8[8];
#pragma unroll
    for (int j = 0; j < 8; j++) A8[j] = A_s[tx * 8 + j];

    float bv[8], sv[8]; int bi[8];
#pragma unroll
    for (int j = 0; j < 8; j++) { bv[j] = 3.4e38f; sv[j] = 3.4e38f; bi[j] = 0; }

    for (int k0 = 0; k0 < KCODES; k0 += TKW) {
        unsigned long long acc[4][4];          // 4 px-pairs x 4 codes
#pragma unroll
        for (int i = 0; i < 4; i++)
#pragma unroll
            for (int c = 0; c < 4; c++) acc[i][c] = 0ull;

        for (int d0 = 0; d0 < DDIM; d0 += DCW) {
            __syncthreads();
            {   // stage e chunk transposed: e_s[d][k], 128 codes x 32 d
                int code = tid >> 1;           // 0..127
                int q    = tid & 1;
                const float* erow = emb + (size_t)(k0 + code) * DDIM + d0;
#pragma unroll
                for (int jj = 0; jj < 4; jj++) {
                    int m = q + 2 * jj;        // float4 index 0..7
                    float4 v = *(const float4*)(erow + 4 * m);
                    e_s[(4 * m + 0) * SEW + code] = v.x;
                    e_s[(4 * m + 1) * SEW + code] = v.y;
                    e_s[(4 * m + 2) * SEW + code] = v.z;
                    e_s[(4 * m + 3) * SEW + code] = v.w;
                }
            }
            __syncthreads();

            const float* zrow = z_s + (size_t)d0 * BPW + tx * 8;
            const float* erow = e_s + ty * 4;
#pragma unroll 4
            for (int d = 0; d < DCW; d++) {
                ulonglong2 za = *(const ulonglong2*)(zrow + d * BPW);
                ulonglong2 zb = *(const ulonglong2*)(zrow + d * BPW + 4);
                float4 ea = *(const float4*)(erow + d * SEW);
                unsigned long long zz[4] = {za.x, za.y, zb.x, zb.y};
                unsigned long long ed[4];
                DUP2(ed[0], ea.x); DUP2(ed[1], ea.y);
                DUP2(ed[2], ea.z); DUP2(ed[3], ea.w);
#pragma unroll
                for (int i = 0; i < 4; i++)
#pragma unroll
                    for (int c = 0; c < 4; c++)
                        FMA2(acc[i][c], zz[i], ed[c]);
            }
        }

        // epilogue: exact reference fp32 dist; ascending k, strict '<'
#pragma unroll
        for (int c = 0; c < 4; c++) {
            int k = k0 + ty * 4 + c;
            float en = en_s[k];
#pragma unroll
            for (int i = 0; i < 4; i++) {
                float lo = __uint_as_float((unsigned)(acc[i][c] & 0xffffffffull));
                float hi = __uint_as_float((unsigned)(acc[i][c] >> 32));
                float d0v = __fadd_rn(__fsub_rn(A8[2*i],   __fmul_rn(2.0f, lo)), en);
                float d1v = __fadd_rn(__fsub_rn(A8[2*i+1], __fmul_rn(2.0f, hi)), en);
                int j0 = 2 * i, j1 = 2 * i + 1;
                if (d0v < bv[j0]) { sv[j0] = bv[j0]; bv[j0] = d0v; bi[j0] = k; }
                else if (d0v < sv[j0]) sv[j0] = d0v;
                if (d1v < bv[j1]) { sv[j1] = bv[j1]; bv[j1] = d1v; bi[j1] = k; }
                else if (d1v < sv[j1]) sv[j1] = d1v;
            }
        }
    }

    // ---- cross-thread merge (32 ty contributors per pixel) ----
    __syncthreads();
    float* rv = z_s;                     // reuse: [64][33]
    int*   ri = (int*)(z_s + 2112);
    float* rs = z_s + 4224;
#pragma unroll
    for (int j = 0; j < 8; j++) {
        int p = tx * 8 + j;
        rv[p * 33 + ty] = bv[j];
        ri[p * 33 + ty] = bi[j];
        rs[p * 33 + ty] = sv[j];
    }
    __syncthreads();
    if (tid < BPW) {
        float b = rv[tid * 33]; int x0 = ri[tid * 33]; float s = rs[tid * 33];
#pragma unroll
        for (int t = 1; t < 32; t++) {
            float v = rv[tid * 33 + t]; int x = ri[tid * 33 + t];
            float s2 = rs[tid * 33 + t];
            if (v < b || (v == b && x < x0)) { s = fminf(b, s2); b = v; x0 = x; }
            else s = fminf(s, v);
        }
        out[n0 + tid] = (float)x0;
        if (__fsub_rn(s, b) < MARGIN) {
            int idx = atomicAdd(&g_nflag, 1);
            g_flags[idx] = n0 + tid;
        }
    }
}

// ---------------------------------------------------------------------------
// Tiled fixup: 16 flagged px/block, double-float dots (proven recipe).
// tx = tid&3 (4 groups x 4 px = 16), ty = tid>>2 (64 groups x 2 codes = 128).
// ---------------------------------------------------------------------------
#define FPX 16
#define FTK 128
#define FDC 16
#define FSE 132

__global__ __launch_bounds__(THREADS)
void fixup2(const float* __restrict__ z, const float* __restrict__ emb,
            float* __restrict__ out) {
    __shared__ float z_s[DDIM * FPX];   // 16 KB
    __shared__ float e_s[FDC * FSE];    // 8.4 KB
    __shared__ float en_s[KCODES];      // 4 KB
    __shared__ int   pl_s[FPX];
    __shared__ float A_s[FPX];

    const int tid = threadIdx.x;
    const int tx  = tid & 3;
    const int ty  = tid >> 2;

    for (int i = tid; i < KCODES; i += THREADS) en_s[i] = g_enorm[i];

    for (int base = blockIdx.x * FPX; base < g_nflag; base += gridDim.x * FPX) {
        int nhere = g_nflag - base; if (nhere > FPX) nhere = FPX;
        __syncthreads();                 // protect smem reuse across chunks
        if (tid < FPX) {
            int p = g_flags[base + (tid < nhere ? tid : 0)];
            pl_s[tid] = p;
            A_s[tid]  = g_A[p];
        }
        __syncthreads();
        for (int i = tid; i < DDIM * FPX; i += THREADS) {
            int d = i >> 4, q = i & 15;
            int p = pl_s[q];
            z_s[i] = z[(size_t)(p >> 12) * (DDIM * 4096)
                       + (size_t)d * 4096 + (p & 4095)];
        }
        __syncthreads();

        float bv[4]; int bi[4];
#pragma unroll
        for (int j = 0; j < 4; j++) { bv[j] = 3.4e38f; bi[j] = 0; }

        for (int k0 = 0; k0 < KCODES; k0 += FTK) {
            float hi[4][2], lo[4][2];
#pragma unroll
            for (int j = 0; j < 4; j++)
#pragma unroll
                for (int c = 0; c < 2; c++) { hi[j][c] = 0.f; lo[j][c] = 0.f; }

            for (int d0 = 0; d0 < DDIM; d0 += FDC) {
                __syncthreads();
                {   // stage e chunk [16 d][128 codes]
                    int code = tid >> 1, q = tid & 1;
                    const float* erow = emb + (size_t)(k0 + code) * DDIM + d0;
#pragma unroll
                    for (int jj = 0; jj < 2; jj++) {
                        int m = q + 2 * jj;      // 0..3
                        float4 v = *(const float4*)(erow + 4 * m);
                        e_s[(4 * m + 0) * FSE + code] = v.x;
                        e_s[(4 * m + 1) * FSE + code] = v.y;
                        e_s[(4 * m + 2) * FSE + code] = v.z;
                        e_s[(4 * m + 3) * FSE + code] = v.w;
                    }
                }
                __syncthreads();

                const float* zrow = z_s + (size_t)d0 * FPX + tx * 4;
                const float* erow = e_s + ty * 2;
#pragma unroll 2
                for (int d = 0; d < FDC; d++) {
                    float4 zz = *(const float4*)(zrow + d * FPX);
                    float2 ee = *(const float2*)(erow + d * FSE);
                    float zf[4] = {zz.x, zz.y, zz.z, zz.w};
                    float ef[2] = {ee.x, ee.y};
#pragma unroll
                    for (int j = 0; j < 4; j++)
#pragma unroll
                        for (int c = 0; c < 2; c++) {
                            float x = zf[j], y = ef[c];
                            float pm = __fmul_rn(x, y);
                            float e1 = fmaf(x, y, -pm);
                            float t  = __fadd_rn(hi[j][c], pm);
                            float v  = __fsub_rn(t, hi[j][c]);
                            float e2 = __fadd_rn(
                                __fsub_rn(hi[j][c], __fsub_rn(t, v)),
                                __fsub_rn(pm, v));
                            hi[j][c] = t;
                            lo[j][c] = __fadd_rn(lo[j][c], __fadd_rn(e1, e2));
                        }
                }
            }
#pragma unroll
            for (int c = 0; c < 2; c++) {
                int k = k0 + ty * 2 + c;
                float en = en_s[k];
#pragma unroll
                for (int j = 0; j < 4; j++) {
                    float M  = __fadd_rn(hi[j][c], lo[j][c]);
                    float dv = __fadd_rn(
                        __fsub_rn(A_s[tx * 4 + j], __fmul_rn(2.0f, M)), en);
                    if (dv < bv[j]) { bv[j] = dv; bi[j] = k; }
                }
            }
        }

        // cross-thread merge (64 ty per pixel), tie -> smallest index
        __syncthreads();
        float* rv = z_s;                   // reuse: [16][65]
        int*   ri = (int*)(z_s + 1040);
#pragma unroll
        for (int j = 0; j < 4; j++) {
            int p = tx * 4 + j;
            rv[p * 65 + ty] = bv[j];
            ri[p * 65 + ty] = bi[j];
        }
        __syncthreads();
        if (tid < nhere) {
            float b = rv[tid * 65]; int x0 = ri[tid * 65];
#pragma unroll
            for (int t = 1; t < 64; t++) {
                float v = rv[tid * 65 + t]; int x = ri[tid * 65 + t];
                if (v < b || (v == b && x < x0)) { b = v; x0 = x; }
            }
            out[pl_s[tid]] = (float)x0;
        }
    }
}

// ---------------------------------------------------------------------------
extern "C" void kernel_launch(void* const* d_in, const int* in_sizes, int n_in,
                              void* d_out, int out_size) {
    const float* z   = nullptr;
    const float* emb = nullptr;
    for (int i = 0; i < n_in; i++) {
        long s = (long)in_sizes[i];
        if (s == 16777216L || s == 67108864L)   z   = (const float*)d_in[i];
        else if (s == 262144L || s == 1048576L) emb = (const float*)d_in[i];
    }
    if (!z)   z   = (const float*)d_in[0];
    if (!emb) emb = (const float*)d_in[n_in > 1 ? 1 : 0];
    float* out = (float*)d_out;

    reset_kernel<<<1, 32>>>();
    enorm_kernel<<<KCODES / 128, 128>>>(emb);
    anorm_kernel<<<NPIX / 128, 128>>>(z);

    size_t smw = (size_t)SMEMW_FLOATS * sizeof(float);
    cudaFuncSetAttribute(vq_wide, cudaFuncAttributeMaxDynamicSharedMemorySize,
                         (int)smw);
    vq_wide<<<NPIX / BPW, THREADS, smw>>>(z, emb, out);
    fixup2<<<1024, THREADS>>>(z, emb, out);
}